// round 8
// baseline (speedup 1.0000x reference)
#include <cuda_runtime.h>
#include <cuda.h>
#include <math.h>
#include <stdint.h>

// YOLO loss: preds [16384,7,7,30] f32, labels same, scalar f32 out.
// Warp-autonomous double-buffered pipeline with cp.async.bulk (UBLKCP):
//   512 blocks x 128 threads (4 warps). Each warp owns a private smem slice
//   (2 stages x [28 cells x 30 f32 preds | labels] = 13440 B) and two
//   mbarriers (one per stage). Lane 0 issues bulk copies; all lanes wait on
//   mbarrier parity with acquire. 2048 warp-streams x 14 tiles each (exact).
//   R8 fix: responsible LABEL box is box idx (lr = take(lb)), not box 0.
//   Block reduce + ticket atomic; last block reduces 512 partials in double.

#define SIDE 7
#define NBATCH 16384
#define NTHREADS 128
#define NWARPS 4
#define TILE_CELLS 28
#define TILE_FLOATS (TILE_CELLS * 30)        // 840
#define TILE_BYTES (TILE_FLOATS * 4)         // 3360 B per array
#define STAGE_BYTES (2 * TILE_BYTES)         // 6720 B (preds|labels)
#define WARP_BYTES (2 * STAGE_BYTES)         // 13440 B (2 stages)
#define SMEM_BYTES (NWARPS * WARP_BYTES)     // 53760 B dynamic
#define PGRID 512
#define NSTREAMS (PGRID * NWARPS)            // 2048
#define TILES_PER_STREAM 14                  // 28672 / 2048 exactly

__device__ float g_partials[PGRID];
__device__ unsigned int g_ticket = 0;

__device__ __forceinline__ void mbar_init(uint32_t mbar, uint32_t count) {
    asm volatile("mbarrier.init.shared.b64 [%0], %1;"
                 :: "r"(mbar), "r"(count) : "memory");
}
__device__ __forceinline__ void mbar_expect_tx(uint32_t mbar, uint32_t tx) {
    asm volatile("mbarrier.arrive.expect_tx.shared.b64 _, [%0], %1;"
                 :: "r"(mbar), "r"(tx) : "memory");
}
// Acquire wait: orders subsequent generic ld.shared after async-proxy writes.
__device__ __forceinline__ void mbar_wait_acq(uint32_t mbar, uint32_t parity) {
    uint32_t done;
    asm volatile(
        "{\n\t.reg .pred p;\n\t"
        "mbarrier.try_wait.parity.acquire.cta.shared::cta.b64 p, [%1], %2;\n\t"
        "selp.b32 %0, 1, 0, p;\n\t}"
        : "=r"(done) : "r"(mbar), "r"(parity) : "memory");
    while (!done) {
        asm volatile(
            "{\n\t.reg .pred p;\n\t"
            "mbarrier.try_wait.parity.acquire.cta.shared::cta.b64 p, [%1], %2, 0x989680;\n\t"
            "selp.b32 %0, 1, 0, p;\n\t}"
            : "=r"(done) : "r"(mbar), "r"(parity) : "memory");
    }
}
__device__ __forceinline__ void bulk_cp(uint32_t sdst, const void* gsrc,
                                        uint32_t bytes, uint32_t mbar) {
    asm volatile(
        "cp.async.bulk.shared::cluster.global.mbarrier::complete_tx::bytes "
        "[%0], [%1], %2, [%3];"
        :: "r"(sdst), "l"(gsrc), "r"(bytes), "r"(mbar) : "memory");
}
__device__ __forceinline__ void fence_async() {
    asm volatile("fence.proxy.async.shared::cta;" ::: "memory");
}

// Issue one tile's two bulk copies into a stage (lane 0 only).
__device__ __forceinline__ void issue_tile(uint32_t stage_base, uint32_t mbar,
                                           const char* preds, const char* labels,
                                           int tile)
{
    const long long off = (long long)tile * TILE_BYTES;
    mbar_expect_tx(mbar, STAGE_BYTES);
    bulk_cp(stage_base, preds + off, TILE_BYTES, mbar);
    bulk_cp(stage_base + TILE_BYTES, labels + off, TILE_BYTES, mbar);
}

__device__ __forceinline__ float cell_loss(const float* __restrict__ p,
                                           const float* __restrict__ l)
{
    const float s = 1.0f / (float)SIDE;
    float lconf = l[4];
    if (lconf == 0.0f) {
        // noobj: labels conf (indices 4 and 9) both zero here
        float d0 = p[4];
        float d1 = p[9];
        return 0.5f * (d0 * d0 + d1 * d1);
    }

    // 8B-aligned (cell stride 120 B): read via float2.
    const float2* p2 = (const float2*)p;
    const float2* l2 = (const float2*)l;

    float2 pa01 = p2[0], pa23 = p2[1], pa45 = p2[2], pa67 = p2[3], pa89 = p2[4];
    float2 la01 = l2[0], la23 = l2[1], la45 = l2[2], la67 = l2[3], la89 = l2[4];

    // IoU target: label box 0 only (lbox = lb[..., 0:1, :])
    float l1x = la01.x * s - 0.5f * la23.x;
    float l1y = la01.y * s - 0.5f * la23.y;
    float l2x = la01.x * s + 0.5f * la23.x;
    float l2y = la01.y * s + 0.5f * la23.y;
    float la  = la23.x * la23.y;

    // pred boxes: b0 = {pa01.x, pa01.y, pa23.x, pa23.y, pa45.x}
    //             b1 = {pa45.y, pa67.x, pa67.y, pa89.x, pa89.y}
    float bx[2] = { pa01.x, pa45.y };
    float by[2] = { pa01.y, pa67.x };
    float bw[2] = { pa23.x, pa67.y };
    float bh[2] = { pa23.y, pa89.x };
    float bc[2] = { pa45.x, pa89.y };

    // label boxes, same layout
    float lx[2] = { la01.x, la45.y };
    float ly[2] = { la01.y, la67.x };
    float lw[2] = { la23.x, la67.y };
    float lh[2] = { la23.y, la89.x };

    float iou[2];
    #pragma unroll
    for (int b = 0; b < 2; b++) {
        float p1x = bx[b] * s - 0.5f * bw[b];
        float p1y = by[b] * s - 0.5f * bh[b];
        float p2x = bx[b] * s + 0.5f * bw[b];
        float p2y = by[b] * s + 0.5f * bh[b];
        float iw = fmaxf(fminf(p2x, l2x) - fmaxf(p1x, l1x), 0.0f);
        float ih = fmaxf(fminf(p2y, l2y) - fmaxf(p1y, l1y), 0.0f);
        float inter = iw * ih;
        float pa = bw[b] * bh[b];
        iou[b] = inter / (pa + la - inter);
    }

    int idx = (iou[1] > iou[0]) ? 1 : 0;   // jnp.argmax: first max wins
    float maxiou = fmaxf(iou[0], iou[1]);

    float dresp = bc[idx] - maxiou;
    float resp  = dresp * dresp;

    float nrc = bc[1 - idx];
    float nr  = nrc * nrc;

    // responsible losses use pred box idx vs LABEL box idx (lr = take(lb))
    float dx = bx[idx] - lx[idx];
    float dy = by[idx] - ly[idx];
    float xy = dx * dx + dy * dy;

    float dw = sqrtf(bw[idx]) - sqrtf(lw[idx]);
    float dh = sqrtf(bh[idx]) - sqrtf(lh[idx]);
    float wh = dw * dw + dh * dh;

    float cls = 0.0f;
    #pragma unroll
    for (int j = 5; j < 15; j++) {
        float2 a = p2[j];
        float2 b = l2[j];
        float d0 = a.x - b.x;
        float d1 = a.y - b.y;
        cls += d0 * d0 + d1 * d1;
    }

    return 5.0f * (xy + wh) + 2.0f * resp + nr + cls;
}

extern __shared__ char smem[];   // [4 warps][2 stages][preds 3360 | labels 3360]

__global__ __launch_bounds__(NTHREADS)
void yolo_bulk_pipe_kernel(const float* __restrict__ preds,
                           const float* __restrict__ labels,
                           float* __restrict__ out)
{
    const int t    = threadIdx.x;
    const int lane = t & 31;
    const int wid  = t >> 5;

    const char* pc = (const char*)preds;
    const char* lc = (const char*)labels;

    __shared__ uint64_t mbar_store[NWARPS * 2];
    const uint32_t mbar0 = (uint32_t)__cvta_generic_to_shared(&mbar_store[wid * 2]);
    const uint32_t mbar1 = mbar0 + 8;

    const uint32_t warp_base =
        (uint32_t)__cvta_generic_to_shared(smem) + (uint32_t)wid * WARP_BYTES;
    const char* warp_gen = smem + wid * WARP_BYTES;

    const int gwid = blockIdx.x * NWARPS + wid;   // 0..2047

    if (lane == 0) {
        mbar_init(mbar0, 1);
        mbar_init(mbar1, 1);
        fence_async();
    }
    __syncwarp();

    float acc_cell = 0.0f;

    // Prologue: tiles 0 and 1 into stages 0 and 1.
    if (lane == 0) {
        issue_tile(warp_base, mbar0, pc, lc, gwid);
        issue_tile(warp_base + STAGE_BYTES, mbar1, pc, lc, gwid + NSTREAMS);
    }

    uint32_t phase[2] = {0u, 0u};

    #pragma unroll 1
    for (int i = 0; i < TILES_PER_STREAM; i++) {
        const int s = i & 1;
        mbar_wait_acq(s ? mbar1 : mbar0, phase[s]);
        phase[s] ^= 1u;

        if (lane < TILE_CELLS) {
            const float* sp = (const float*)(warp_gen + s * STAGE_BYTES);
            const float* sl = sp + TILE_FLOATS;
            acc_cell += cell_loss(sp + lane * 30, sl + lane * 30);
        }
        __syncwarp();   // all lanes done reading before stage refill

        if (i + 2 < TILES_PER_STREAM && lane == 0) {
            issue_tile(warp_base + (uint32_t)s * STAGE_BYTES,
                       s ? mbar1 : mbar0,
                       pc, lc, gwid + (i + 2) * NSTREAMS);
        }
    }

    // Block reduction: warp shuffle tree then cross-warp via smem.
    float v = acc_cell;
    #pragma unroll
    for (int off = 16; off > 0; off >>= 1)
        v += __shfl_down_sync(0xFFFFFFFFu, v, off);

    __shared__ float wsum[NWARPS];
    if (lane == 0) wsum[wid] = v;
    __syncthreads();

    __shared__ bool is_last;
    if (t == 0) {
        float bacc = 0.0f;
        #pragma unroll
        for (int w = 0; w < NWARPS; w++) bacc += wsum[w];
        g_partials[blockIdx.x] = bacc;
        __threadfence();
        unsigned int ticket = atomicAdd(&g_ticket, 1u);
        is_last = (ticket == PGRID - 1);
    }
    __syncthreads();

    // Last-arriving block: deterministic final reduction over 512 partials.
    if (is_last) {
        double acc = 0.0;
        #pragma unroll 1
        for (int i = t; i < PGRID; i += NTHREADS)
            acc += (double)g_partials[i];

        #pragma unroll
        for (int off = 16; off > 0; off >>= 1)
            acc += __shfl_down_sync(0xFFFFFFFFu, acc, off);

        __shared__ double dsum[NWARPS];
        if (lane == 0) dsum[wid] = acc;
        __syncthreads();

        if (t == 0) {
            double total = 0.0;
            #pragma unroll
            for (int w = 0; w < NWARPS; w++) total += dsum[w];
            out[0] = (float)(total / (double)NBATCH);
            g_ticket = 0;   // reset for next graph replay
        }
    }
}

extern "C" void kernel_launch(void* const* d_in, const int* in_sizes, int n_in,
                              void* d_out, int out_size)
{
    const float* preds  = (const float*)d_in[0];
    const float* labels = (const float*)d_in[1];
    float* out = (float*)d_out;

    static bool attr_set = false;
    if (!attr_set) {
        cudaFuncSetAttribute(yolo_bulk_pipe_kernel,
                             cudaFuncAttributeMaxDynamicSharedMemorySize,
                             SMEM_BYTES);
        attr_set = true;
    }

    yolo_bulk_pipe_kernel<<<PGRID, NTHREADS, SMEM_BYTES>>>(preds, labels, out);
}